// round 13
// baseline (speedup 1.0000x reference)
#include <cuda_runtime.h>
#include <cuda_bf16.h>
#include <math.h>
#include <stdint.h>

// Problem constants
#define BATCH 4
#define SEQ   2048
#define EMB   1024
#define HEADS 16
#define HD    64
#define NTOK  (BATCH*SEQ)     // 8192
#define BH    (BATCH*HEADS)   // 64
#define NQUBITS 6
#define PLA   4194304u        // BH*SEQ*HD/2 = plane stride (u32) for Q/K activations
#define PLB   524288u         // EMB*EMB/2  = plane stride (u32) for weights

// ---------------- scratch (static device globals; no allocation) ----------------
__device__ uint32_t g_Qp[2*PLA];   // Q bf16x2 planes (b,h,s,d-pairs)
__device__ uint32_t g_Kp[2*PLA];   // K bf16x2 planes
__device__ float    g_Vh[BH*SEQ*HD]; // V tf32-rounded fp32 (b,h,s,d)
__device__ float    g_O[NTOK*EMB];   // attention output fp32 (b,s,e)
__device__ uint32_t g_Wqp[2*PLB];  // effective Q weight, bf16x2 planes [2][1024][512]
__device__ uint32_t g_Wkp[2*PLB];
__device__ uint32_t g_Wvp[2*PLB];
__device__ uint32_t g_Wop[2*PLB];
__device__ float g_Mq[HD*HD];
__device__ float g_Mk[HD*HD];
__device__ float g_beq[HD];
__device__ float g_bek[HD];
__device__ float g_bqf[EMB];
__device__ float g_bkf[EMB];

// ---------------- helpers ----------------
__device__ __forceinline__ uint32_t f2tf(float x) {
    uint32_t u; asm("cvt.rna.tf32.f32 %0, %1;" : "=r"(u) : "f"(x)); return u;
}
__device__ __forceinline__ uint32_t fbits(float x) { return __float_as_uint(x); }
__device__ __forceinline__ void mma_tf32(float* d, const uint32_t* a, const uint32_t* b) {
    asm volatile("mma.sync.aligned.m16n8k8.row.col.f32.tf32.tf32.f32 "
        "{%0,%1,%2,%3}, {%4,%5,%6,%7}, {%8,%9}, {%0,%1,%2,%3};"
        : "+f"(d[0]), "+f"(d[1]), "+f"(d[2]), "+f"(d[3])
        : "r"(a[0]), "r"(a[1]), "r"(a[2]), "r"(a[3]), "r"(b[0]), "r"(b[1]));
}
__device__ __forceinline__ void mma_bf16(float* d, const uint32_t* a, const uint32_t* b) {
    asm volatile("mma.sync.aligned.m16n8k16.row.col.f32.bf16.bf16.f32 "
        "{%0,%1,%2,%3}, {%4,%5,%6,%7}, {%8,%9}, {%0,%1,%2,%3};"
        : "+f"(d[0]), "+f"(d[1]), "+f"(d[2]), "+f"(d[3])
        : "r"(a[0]), "r"(a[1]), "r"(a[2]), "r"(a[3]), "r"(b[0]), "r"(b[1]));
}
// split a float pair into bf16x2 hi + bf16x2 lo (residual)
__device__ __forceinline__ void pack2(float x, float y, uint32_t* hi, uint32_t* lo) {
    __nv_bfloat162 h = __float22bfloat162_rn(make_float2(x, y));
    float2 hf = __bfloat1622float2(h);
    __nv_bfloat162 l = __float22bfloat162_rn(make_float2(x - hf.x, y - hf.y));
    *hi = *reinterpret_cast<uint32_t*>(&h);
    *lo = *reinterpret_cast<uint32_t*>(&l);
}
__device__ __forceinline__ void cp16(void* s, const void* g) {
    asm volatile("cp.async.cg.shared.global [%0], [%1], 16;"
        :: "r"((uint32_t)__cvta_generic_to_shared(s)), "l"(g));
}
__device__ __forceinline__ void cp_commit() { asm volatile("cp.async.commit_group;"); }
__device__ __forceinline__ void cp_wait1() { asm volatile("cp.async.wait_group 1;"); }
__device__ __forceinline__ void cp_wait0() { asm volatile("cp.async.wait_group 0;"); }

// ---------------- quantum layer composition (fp32-exact) ----------------
__global__ __launch_bounds__(256) void quantum_compose(
    const float* __restrict__ theta, const float* __restrict__ phi,
    const float* __restrict__ preW, const float* __restrict__ preb,
    const float* __restrict__ postW, const float* __restrict__ postb,
    float* __restrict__ Meff, float* __restrict__ beff)
{
    __shared__ float A[HD][HD+1];
    __shared__ float bv[HD];
    int t = threadIdx.x;
    for (int idx = t; idx < HD*HD; idx += 256) A[idx >> 6][idx & 63] = preW[idx];
    if (t < HD) bv[t] = preb[t];
    __syncthreads();
    for (int i = 0; i < NQUBITS; i++) {
        float th = theta[i], ph = phi[i];
        float c = cosf(th), s = sinf(th), cp = cosf(ph);
        for (int w = t; w < 32*HD; w += 256) {
            int p = w >> 6, col = w & 63;
            int low = p & ((1 << i) - 1);
            int i0 = ((p >> i) << (i + 1)) | low;
            int i1 = i0 | (1 << i);
            float x0 = A[i0][col], x1 = A[i1][col];
            A[i0][col] = c * x0 - s * x1;
            A[i1][col] = cp * (s * x0 + c * x1);
        }
        if (t < 32) {
            int p = t;
            int low = p & ((1 << i) - 1);
            int i0 = ((p >> i) << (i + 1)) | low;
            int i1 = i0 | (1 << i);
            float x0 = bv[i0], x1 = bv[i1];
            bv[i0] = c * x0 - s * x1;
            bv[i1] = cp * (s * x0 + c * x1);
        }
        __syncthreads();
    }
    for (int idx = t; idx < HD*HD; idx += 256) {
        int i = idx >> 6, j = idx & 63;
        float acc = (i == j) ? 1.0f : 0.0f;
        #pragma unroll 8
        for (int d = 0; d < HD; d++) acc += postW[i*HD + d] * A[d][j];
        Meff[idx] = acc;
    }
    if (t < HD) {
        float acc = postb[t];
        #pragma unroll 8
        for (int d = 0; d < HD; d++) acc += postW[t*HD + d] * bv[d];
        beff[t] = acc;
    }
}

// weff bf16x2 planes
__global__ __launch_bounds__(256) void make_weff_bf(
    const float* __restrict__ M, const float* __restrict__ w, uint32_t* __restrict__ wp)
{
    int r = blockIdx.y;
    int jp = blockIdx.x * 256 + threadIdx.x;
    int h = r >> 6, i = r & 63;
    __shared__ float Mrow[HD];
    if (threadIdx.x < HD) Mrow[threadIdx.x] = M[i*HD + threadIdx.x];
    __syncthreads();
    float a0 = 0.0f, a1 = 0.0f;
    int j = jp * 2;
    #pragma unroll 8
    for (int d = 0; d < HD; d++) {
        float m = Mrow[d];
        a0 += m * w[(h*HD + d) * EMB + j];
        a1 += m * w[(h*HD + d) * EMB + j + 1];
    }
    size_t idx = (size_t)r * 512 + jp;
    pack2(a0, a1, wp + idx, wp + PLB + idx);
}

__global__ __launch_bounds__(256) void make_beff(
    const float* __restrict__ M, const float* __restrict__ beff,
    const float* __restrict__ b_in, float* __restrict__ bfull)
{
    int r = blockIdx.x * 256 + threadIdx.x;
    int h = r >> 6, i = r & 63;
    float acc = beff[i];
    #pragma unroll 8
    for (int d = 0; d < HD; d++) acc += M[i*HD + d] * b_in[h*HD + d];
    bfull[r] = acc;
}

// elementwise fp32 -> bf16x2 hi/lo planes (weights only now)
__global__ __launch_bounds__(256) void split2bf(
    const float* __restrict__ x, uint32_t* __restrict__ planes, uint32_t plstride, int npairs)
{
    int i = blockIdx.x * 256 + threadIdx.x;
    if (i >= npairs) return;
    float2 v = reinterpret_cast<const float2*>(x)[i];
    pack2(v.x, v.y, planes + i, planes + plstride + i);
}

// ---------------- bf16 split GEMM: A fp32 (split at frag build), B pre-split planes -----
// C(8192x1024) = X @ W^T + bias. BM=BN=128, k-slab 16, 8 warps (2x4), warp tile 64x32.
// Per k16 per warp-tile: 3 mma.m16n8k16 (A-hi*B-hi + A-lo*B-hi + A-hi*B-lo).
// mode: 0 fp32 flat; 1 bf16x2 plane scatter (b,h,s,d); 2 tf32-rounded fp32 scatter.
#define BKP 20
__global__ __launch_bounds__(256) void gemm_bs(
    const float* __restrict__ X, const uint32_t* __restrict__ Bw,
    const float* __restrict__ bias, void* __restrict__ outv, int mode)
{
    __shared__ float    sA[2][128*BKP];    // fp32 A slabs, stride 20
    __shared__ uint32_t sB[2][2*128*12];   // bf16x2 B planes, stride 12
    int t = threadIdx.x;
    int lane = t & 31, w = t >> 5;
    int gid = lane >> 2, tig = lane & 3;
    int wm = w >> 2, wn = w & 3;
    int m0 = blockIdx.y * 128, n0 = blockIdx.x * 128;

    float acc[4][4][4];
    #pragma unroll
    for (int i = 0; i < 4; i++)
        #pragma unroll
        for (int j = 0; j < 4; j++)
            #pragma unroll
            for (int r = 0; r < 4; r++) acc[i][j][r] = 0.0f;

    const int NSLAB = EMB / 16;  // 64
    // stage fill: A 512 chunks (128 rows x 4 float4), B 512 chunks (2 planes x 128 x 2)
    #define GS_FILL(st, ks)                                                        \
        do {                                                                       \
            _Pragma("unroll")                                                      \
            for (int p = 0; p < 4; p++) {                                          \
                int c = t + p * 256;                                               \
                if (c < 512) {                                                     \
                    int row = c >> 2, c4 = c & 3;                                  \
                    cp16(&sA[st][row*BKP + c4*4],                                  \
                         X + (size_t)(m0+row)*EMB + (ks)*16 + c4*4);               \
                } else {                                                           \
                    int c2 = c - 512;                                              \
                    int plane = c2 >> 8, row = (c2 >> 1) & 127, half = c2 & 1;     \
                    cp16(&sB[st][plane*1536 + row*12 + half*4],                    \
                         Bw + (size_t)plane*PLB + (size_t)(n0+row)*512             \
                            + (ks)*8 + half*4);                                    \
                }                                                                  \
            }                                                                      \
            cp_commit();                                                           \
        } while (0)

    GS_FILL(0, 0);

    for (int s = 0; s < NSLAB; s++) {
        if (s + 1 < NSLAB) {
            GS_FILL((s+1)&1, s+1);
            cp_wait1();
        } else {
            cp_wait0();
        }
        __syncthreads();
        const float* dA = sA[s&1];
        const uint32_t* dB = sB[s&1];

        uint32_t af[2][4][4], bfr[2][4][2];
        #pragma unroll
        for (int mt = 0; mt < 4; mt++) {
            int mr = wm*64 + mt*16;
            float2 xa = *reinterpret_cast<const float2*>(&dA[(mr+gid  )*BKP + tig*2    ]);
            float2 xb = *reinterpret_cast<const float2*>(&dA[(mr+gid+8)*BKP + tig*2    ]);
            float2 xc = *reinterpret_cast<const float2*>(&dA[(mr+gid  )*BKP + 8 + tig*2]);
            float2 xd = *reinterpret_cast<const float2*>(&dA[(mr+gid+8)*BKP + 8 + tig*2]);
            pack2(xa.x, xa.y, &af[0][mt][0], &af[1][mt][0]);
            pack2(xb.x, xb.y, &af[0][mt][1], &af[1][mt][1]);
            pack2(xc.x, xc.y, &af[0][mt][2], &af[1][mt][2]);
            pack2(xd.x, xd.y, &af[0][mt][3], &af[1][mt][3]);
        }
        #pragma unroll
        for (int nt = 0; nt < 4; nt++) {
            int nc = wn*32 + nt*8;
            bfr[0][nt][0] = dB[        (nc+gid)*12 + tig  ];
            bfr[0][nt][1] = dB[        (nc+gid)*12 + tig+4];
            bfr[1][nt][0] = dB[1536 + (nc+gid)*12 + tig  ];
            bfr[1][nt][1] = dB[1536 + (nc+gid)*12 + tig+4];
        }
        #pragma unroll
        for (int mt = 0; mt < 4; mt++)
            #pragma unroll
            for (int nt = 0; nt < 4; nt++) {
                mma_bf16(acc[mt][nt], af[0][mt], bfr[0][nt]);
                mma_bf16(acc[mt][nt], af[1][mt], bfr[0][nt]);
                mma_bf16(acc[mt][nt], af[0][mt], bfr[1][nt]);
            }
        __syncthreads();
    }

    // epilogue
    #pragma unroll
    for (int mt = 0; mt < 4; mt++) {
        int m = m0 + wm*64 + mt*16 + gid;
        #pragma unroll
        for (int nt = 0; nt < 4; nt++) {
            int n = n0 + wn*32 + nt*8 + tig*2;
            float b0 = bias[n], b1 = bias[n+1];
            float va0 = acc[mt][nt][0] + b0, va1 = acc[mt][nt][1] + b1;
            float vb0 = acc[mt][nt][2] + b0, vb1 = acc[mt][nt][3] + b1;
            if (mode == 0) {
                float* out = (float*)outv;
                *reinterpret_cast<float2*>(&out[(size_t)m * EMB + n]) = make_float2(va0, va1);
                *reinterpret_cast<float2*>(&out[(size_t)(m+8) * EMB + n]) = make_float2(vb0, vb1);
            } else {
                int h = n >> 6;
                int bb0 = m >> 11, s0 = m & 2047;
                int m1 = m + 8;
                int bb1 = m1 >> 11, s1 = m1 & 2047;
                if (mode == 1) {
                    int dp = (n & 63) >> 1;
                    size_t i0 = ((size_t)(bb0*HEADS + h) * SEQ + s0) * 32 + dp;
                    size_t i1 = ((size_t)(bb1*HEADS + h) * SEQ + s1) * 32 + dp;
                    uint32_t* O0 = (uint32_t*)outv;
                    pack2(va0, va1, O0 + i0, O0 + PLA + i0);
                    pack2(vb0, vb1, O0 + i1, O0 + PLA + i1);
                } else { // mode 2: V tf32-rounded fp32 (b,h,s,d)
                    float* out = (float*)outv;
                    int d = n & 63;
                    size_t f0 = ((size_t)(bb0*HEADS + h) * SEQ + s0) * HD + d;
                    size_t f1 = ((size_t)(bb1*HEADS + h) * SEQ + s1) * HD + d;
                    *reinterpret_cast<float2*>(&out[f0]) =
                        make_float2(__uint_as_float(f2tf(va0)), __uint_as_float(f2tf(va1)));
                    *reinterpret_cast<float2*>(&out[f1]) =
                        make_float2(__uint_as_float(f2tf(vb0)), __uint_as_float(f2tf(vb1)));
                }
            }
        }
    }
}

// ---------------- flash attention: bf16x2 QK + tf32 PV, KV tile 64 ----------------
// Block: 128 q-rows of one (b,h), 8 warps x 16 rows. KV tiles of 64. Register softmax.
// smem (u32):
//   stage s at s*9216: K0[64][36] @+0 (2304), K1 @+2304, V fp32[64][72] @+4608 (4608)
//   PS fp32 [128][68] @ 18432 (8704)   total 27136 u32 = 108544 B
//   Q planes overlay [0, 9216) during prologue
#define FL_SMEM_BYTES 108544
__global__ __launch_bounds__(256) void flash_bf(
    const uint32_t* __restrict__ Qp, const uint32_t* __restrict__ Kp,
    const float* __restrict__ Vh, float* __restrict__ O)
{
    extern __shared__ uint32_t smu[];
    float* PSf = reinterpret_cast<float*>(smu + 18432);

    int t = threadIdx.x;
    int lane = t & 31, w = t >> 5;
    int gid = lane >> 2, tig = lane & 3;
    int bh_ = blockIdx.y;
    int q0 = blockIdx.x * 128;
    size_t bhbase = (size_t)bh_ * SEQ;

    // ---- stage Q planes, extract bf16 fragments to registers ----
    #pragma unroll
    for (int p = 0; p < 8; p++) {
        int c = t + p * 256;
        int plane = c >> 10, row = (c >> 3) & 127, h16 = c & 7;
        cp16(smu + plane*4608 + row*36 + h16*4,
             Qp + (size_t)plane*PLA + (bhbase + q0 + row)*32 + h16*4);
    }
    cp_commit(); cp_wait0();
    __syncthreads();
    uint32_t qa[2][4][4];
    {
        int r0 = w * 16 + gid;
        #pragma unroll
        for (int kq = 0; kq < 4; kq++) {
            int col = kq*8 + tig;
            #pragma unroll
            for (int p = 0; p < 2; p++) {
                const uint32_t* Qb = smu + p*4608;
                qa[p][kq][0] = Qb[(r0  )*36 + col  ];
                qa[p][kq][1] = Qb[(r0+8)*36 + col  ];
                qa[p][kq][2] = Qb[(r0  )*36 + col+4];
                qa[p][kq][3] = Qb[(r0+8)*36 + col+4];
            }
        }
    }
    __syncthreads();   // Q frags in regs; smem free for K/V staging

    float o[8][4];
    #pragma unroll
    for (int i = 0; i < 8; i++)
        #pragma unroll
        for (int j = 0; j < 4; j++) o[i][j] = 0.0f;
    float m0v = -1e30f, m1v = -1e30f, l0 = 0.0f, l1 = 0.0f;
    const float SCALE = 0.125f;

    const int NT = SEQ / 64;  // 32 tiles
    // stage fill: K 1024 chunks (2 planes x 64 rows x 8), V 1024 (64 x 16)
    #define FL_FILL(stg, kt)                                                       \
        do {                                                                       \
            _Pragma("unroll")                                                      \
            for (int p = 0; p < 8; p++) {                                          \
                int c = t + p * 256;                                               \
                if (c < 1024) {                                                    \
                    int plane = c >> 9, row = (c >> 3) & 63, h16 = c & 7;          \
                    cp16((stg) + plane*2304 + row*36 + h16*4,                      \
                         Kp + (size_t)plane*PLA + (bhbase + (kt) + row)*32         \
                            + h16*4);                                              \
                } else {                                                           \
                    int cv = c - 1024;                                             \
                    int row = cv >> 4, h16 = cv & 15;                              \
                    cp16((stg) + 4608 + row*72 + h16*4,                            \
                         Vh + (bhbase + (kt) + row)*HD + h16*4);                   \
                }                                                                  \
            }                                                                      \
            cp_commit();                                                           \
        } while (0)

    FL_FILL(smu, 0);

    for (int tt = 0; tt < NT; tt++) {
        if (tt + 1 < NT) {
            FL_FILL(smu + ((tt+1)&1)*9216, (size_t)(tt+1)*64);
            cp_wait1();
        } else {
            cp_wait0();
        }
        __syncthreads();
        uint32_t* K0 = smu + (tt&1)*9216;
        uint32_t* K1 = K0 + 2304;
        float* Vt = reinterpret_cast<float*>(K0 + 4608);

        // S = Q @ K^T  (16 rows x 64 cols per warp), bf16x2 3-product
        float s4[8][4];
        #pragma unroll
        for (int nt = 0; nt < 8; nt++)
            #pragma unroll
            for (int r = 0; r < 4; r++) s4[nt][r] = 0.0f;
        #pragma unroll
        for (int kq = 0; kq < 4; kq++) {
            int col = kq*8 + tig;
            #pragma unroll
            for (int nt = 0; nt < 8; nt++) {
                int kr = nt*8 + gid;
                uint32_t kb0[2], kb1[2];
                kb0[0] = K0[kr*36 + col  ];
                kb0[1] = K0[kr*36 + col+4];
                kb1[0] = K1[kr*36 + col  ];
                kb1[1] = K1[kr*36 + col+4];
                mma_bf16(s4[nt], qa[0][kq], kb0);
                mma_bf16(s4[nt], qa[1][kq], kb0);
                mma_bf16(s4[nt], qa[0][kq], kb1);
            }
        }

        // register softmax: thread owns rows (w*16+gid) and (+8), 16 cols each
        float tm0 = -1e30f, tm1 = -1e30f;
        #pragma unroll
        for (int nt = 0; nt < 8; nt++) {
            tm0 = fmaxf(tm0, fmaxf(s4[nt][0], s4[nt][1]));
            tm1 = fmaxf(tm1, fmaxf(s4[nt][2], s4[nt][3]));
        }
        tm0 *= SCALE; tm1 *= SCALE;
        tm0 = fmaxf(tm0, __shfl_xor_sync(0xffffffffu, tm0, 1));
        tm0 = fmaxf(tm0, __shfl_xor_sync(0xffffffffu, tm0, 2));
        tm1 = fmaxf(tm1, __shfl_xor_sync(0xffffffffu, tm1, 1));
        tm1 = fmaxf(tm1, __shfl_xor_sync(0xffffffffu, tm1, 2));
        float mn0 = fmaxf(m0v, tm0), mn1 = fmaxf(m1v, tm1);
        float a0s = __expf(m0v - mn0), a1s = __expf(m1v - mn1);
        m0v = mn0; m1v = mn1;
        float rs0 = 0.0f, rs1 = 0.0f;
        int prow = w * 16 + gid;
        #pragma unroll
        for (int nt = 0; nt < 8; nt++) {
            float p0 = __expf(s4[nt][0]*SCALE - mn0);
            float p1 = __expf(s4[nt][1]*SCALE - mn0);
            float p2 = __expf(s4[nt][2]*SCALE - mn1);
            float p3 = __expf(s4[nt][3]*SCALE - mn1);
            rs0 += p0 + p1; rs1 += p2 + p3;
            int col = nt*8 + tig*2;
            PSf[(prow  )*68 + col  ] = __uint_as_float(f2tf(p0));
            PSf[(prow  )*68 + col+1] = __uint_as_float(f2tf(p1));
            PSf[(prow+8)*68 + col  ] = __uint_as_float(f2tf(p2));
            PSf[(prow+8)*68 + col+1] = __uint_as_float(f2tf(p3));
        }
        rs0 += __shfl_xor_sync(0xffffffffu, rs0, 1);
        rs0 += __shfl_xor_sync(0xffffffffu, rs0, 2);
        rs1 += __shfl_xor_sync(0xffffffffu, rs1, 1);
        rs1 += __shfl_xor_sync(0xffffffffu, rs1, 2);
        l0 = l0 * a0s + rs0;
        l1 = l1 * a1s + rs1;
        #pragma unroll
        for (int nt = 0; nt < 8; nt++) {
            o[nt][0] *= a0s; o[nt][1] *= a0s;
            o[nt][2] *= a1s; o[nt][3] *= a1s;
        }
        __syncwarp();

        // O += P @ V   (P and V tf32, 1 mma per k8, 8 k-steps over 64 keys)
        #pragma unroll
        for (int kp = 0; kp < 8; kp++) {
            uint32_t af2[4];
            af2[0] = fbits(PSf[(prow  )*68 + kp*8+tig  ]);
            af2[1] = fbits(PSf[(prow+8)*68 + kp*8+tig  ]);
            af2[2] = fbits(PSf[(prow  )*68 + kp*8+tig+4]);
            af2[3] = fbits(PSf[(prow+8)*68 + kp*8+tig+4]);
            #pragma unroll
            for (int nt = 0; nt < 8; nt++) {
                uint32_t bv2[2];
                bv2[0] = fbits(Vt[(kp*8+tig  )*72 + nt*8+gid]);
                bv2[1] = fbits(Vt[(kp*8+tig+4)*72 + nt*8+gid]);
                mma_tf32(o[nt], af2, bv2);
            }
        }
        __syncthreads();   // all warps done reading this stage before it is refilled
    }

    // epilogue -> O fp32 (b,s,e)
    float inv0 = 1.0f / l0, inv1 = 1.0f / l1;
    int b = bh_ >> 4, h = bh_ & 15;
    int grow = q0 + w * 16 + gid;
    #pragma unroll
    for (int nt = 0; nt < 8; nt++) {
        int col = h*HD + nt*8 + tig*2;
        *reinterpret_cast<float2*>(&O[((size_t)(b*SEQ + grow    )) * EMB + col]) =
            make_float2(o[nt][0]*inv0, o[nt][1]*inv0);
        *reinterpret_cast<float2*>(&O[((size_t)(b*SEQ + grow + 8)) * EMB + col]) =
            make_float2(o[nt][2]*inv1, o[nt][3]*inv1);
    }
}

// ---------------- launch ----------------
extern "C" void kernel_launch(void* const* d_in, const int* in_sizes, int n_in,
                              void* d_out, int out_size)
{
    const float* query   = (const float*)d_in[0];
    const float* key     = (const float*)d_in[1];
    const float* value   = (const float*)d_in[2];
    const float* wq      = (const float*)d_in[3];
    const float* bq      = (const float*)d_in[4];
    const float* wk      = (const float*)d_in[5];
    const float* bk      = (const float*)d_in[6];
    const float* wv      = (const float*)d_in[7];
    const float* bv      = (const float*)d_in[8];
    const float* wo      = (const float*)d_in[9];
    const float* bo      = (const float*)d_in[10];
    const float* q_theta = (const float*)d_in[11];
    const float* q_phi   = (const float*)d_in[12];
    const float* q_preW  = (const float*)d_in[13];
    const float* q_preb  = (const float*)d_in[14];
    const float* q_postW = (const float*)d_in[15];
    const float* q_postb = (const float*)d_in[16];
    const float* k_theta = (const float*)d_in[17];
    const float* k_phi   = (const float*)d_in[18];
    const float* k_preW  = (const float*)d_in[19];
    const float* k_preb  = (const float*)d_in[20];
    const float* k_postW = (const float*)d_in[21];
    const float* k_postb = (const float*)d_in[22];

    static uint32_t *Qp = nullptr, *Kp, *Wqp, *Wkp, *Wvp, *Wop;
    static float *Vh, *O, *Mq, *Mk, *beq, *bek, *bqf, *bkf;
    if (!Qp) {
        cudaGetSymbolAddress((void**)&Qp,  g_Qp);
        cudaGetSymbolAddress((void**)&Kp,  g_Kp);
        cudaGetSymbolAddress((void**)&Vh,  g_Vh);
        cudaGetSymbolAddress((void**)&O,   g_O);
        cudaGetSymbolAddress((void**)&Wqp, g_Wqp);
        cudaGetSymbolAddress((void**)&Wkp, g_Wkp);
        cudaGetSymbolAddress((void**)&Wvp, g_Wvp);
        cudaGetSymbolAddress((void**)&Wop, g_Wop);
        cudaGetSymbolAddress((void**)&Mq,  g_Mq);
        cudaGetSymbolAddress((void**)&Mk,  g_Mk);
        cudaGetSymbolAddress((void**)&beq, g_beq);
        cudaGetSymbolAddress((void**)&bek, g_bek);
        cudaGetSymbolAddress((void**)&bqf, g_bqf);
        cudaGetSymbolAddress((void**)&bkf, g_bkf);
        cudaFuncSetAttribute(flash_bf, cudaFuncAttributeMaxDynamicSharedMemorySize, FL_SMEM_BYTES);
    }

    // 1) fold the quantum layer into effective projection weights/biases (bf16 planes)
    quantum_compose<<<1, 256>>>(q_theta, q_phi, q_preW, q_preb, q_postW, q_postb, Mq, beq);
    quantum_compose<<<1, 256>>>(k_theta, k_phi, k_preW, k_preb, k_postW, k_postb, Mk, bek);
    make_weff_bf<<<dim3(2, EMB), 256>>>(Mq, wq, Wqp);
    make_weff_bf<<<dim3(2, EMB), 256>>>(Mk, wk, Wkp);
    make_beff<<<4, 256>>>(Mq, beq, bq, bqf);
    make_beff<<<4, 256>>>(Mk, bek, bk, bkf);

    // 2) pre-split static weights into bf16x2 planes (activations split in-GEMM)
    split2bf<<<PLB/256, 256>>>(wv, Wvp, PLB, PLB);
    split2bf<<<PLB/256, 256>>>(wo, Wop, PLB, PLB);

    // 3) projections (A = raw fp32); Q/K -> bf16x2 planes, V -> tf32-rounded fp32
    dim3 gg(EMB / 128, NTOK / 128);
    gemm_bs<<<gg, 256>>>(query, Wqp, bqf, Qp, 1);
    gemm_bs<<<gg, 256>>>(key,   Wkp, bkf, Kp, 1);
    gemm_bs<<<gg, 256>>>(value, Wvp, bv,  Vh, 2);

    // 4) attention -> fp32 (b,s,e)
    flash_bf<<<dim3(SEQ / 128, BH), 256, FL_SMEM_BYTES>>>(Qp, Kp, Vh, O);

    // 5) output projection -> fp32 d_out
    gemm_bs<<<gg, 256>>>(O, Wop, bo, (float*)d_out, 0);
}